// round 3
// baseline (speedup 1.0000x reference)
#include <cuda_runtime.h>
#include <math.h>

#define NCH    131072
#define NSTEPS 60
#define HDIM   128

// ---------------------------------------------------------------------------
// Persistent fused EBM Langevin kernel.
// Block: 256 threads (8 warps). Each warp owns a batch of 4 chains and runs
// all 60 MCMC steps on them. Weights w2,w3,w4 live in shared memory with an
// XOR swizzle usable conflict-free in both forward (W) and backward (W^T)
// directions. Per-warp ping-pong activation buffers; only __syncwarp() in the
// hot loop. silu'(a) for layers 1..4 kept in registers for the backward pass.
//
// smem layout (floats):
//   [0      , 16384) w2 swizzled
//   [16384  , 32768) w3 swizzled
//   [32768  , 49152) w4 swizzled
//   [49152  , 57344) per-warp buffers: warp w -> 1024 floats (two 4x128 bufs)
// total = 57344 floats = 229376 bytes (<= 232448 max dynamic smem)
// ---------------------------------------------------------------------------

__device__ __forceinline__ float4 ld4(const float* p) {
    return *reinterpret_cast<const float4*>(p);
}
__device__ __forceinline__ void st4(float* p, float4 v) {
    *reinterpret_cast<float4*>(p) = v;
}

__device__ __forceinline__ void silu_act(float a, float& h, float& sp) {
    float e   = __expf(-a);
    float sig = __fdividef(1.0f, 1.0f + e);
    h  = a * sig;
    sp = sig * (1.0f + a * (1.0f - sig));   // d/da [a*sigmoid(a)]
}

// Forward 128->128 layer: acc_j = b_j + sum_k h_k * W[k][j], then SiLU.
// Ws is the swizzled weight matrix; lane t owns outputs j = 4t..4t+3 for 4 samples.
__device__ __forceinline__ void fwd128(const float* __restrict__ Ws,
                                       const float4 bv,
                                       const float* hin, float* hout,
                                       float sp[4][4], int t)
{
    float acc[4][4];
#pragma unroll
    for (int s = 0; s < 4; s++) {
        acc[s][0] = bv.x; acc[s][1] = bv.y; acc[s][2] = bv.z; acc[s][3] = bv.w;
    }
    const float4* Wv = reinterpret_cast<const float4*>(Ws);
#pragma unroll 2
    for (int k = 0; k < HDIM; k += 4) {
        float4 hv[4];
#pragma unroll
        for (int s = 0; s < 4; s++) hv[s] = ld4(hin + s * HDIM + k);   // broadcast
#pragma unroll
        for (int kk = 0; kk < 4; kk++) {
            const float4 w = Wv[(k + kk) * 32 + (t ^ ((k + kk) & 31))]; // conflict-free
#pragma unroll
            for (int s = 0; s < 4; s++) {
                float h = (&hv[s].x)[kk];
                acc[s][0] = fmaf(h, w.x, acc[s][0]);
                acc[s][1] = fmaf(h, w.y, acc[s][1]);
                acc[s][2] = fmaf(h, w.z, acc[s][2]);
                acc[s][3] = fmaf(h, w.w, acc[s][3]);
            }
        }
    }
#pragma unroll
    for (int s = 0; s < 4; s++) {
        float4 hv;
        silu_act(acc[s][0], hv.x, sp[s][0]);
        silu_act(acc[s][1], hv.y, sp[s][1]);
        silu_act(acc[s][2], hv.z, sp[s][2]);
        silu_act(acc[s][3], hv.w, sp[s][3]);
        st4(hout + s * HDIM + 4 * t, hv);
    }
}

// Backward matmul through W^T: acc[s][i] = sum_j d[s][j] * W[4t+i][j].
// Per-thread column permutation j = jj ^ t + the storage swizzle makes both the
// d-reads and the W-reads bank-conflict-free.
__device__ __forceinline__ void bwdmm(const float* __restrict__ Ws,
                                      const float* din, int t, float acc[4][4])
{
#pragma unroll
    for (int s = 0; s < 4; s++)
#pragma unroll
        for (int i = 0; i < 4; i++) acc[s][i] = 0.0f;

    int rowb[4], swz[4];
#pragma unroll
    for (int i = 0; i < 4; i++) {
        rowb[i] = (4 * t + i) * HDIM;
        swz[i]  = (16 * t + 4 * i) & 127;   // = 4*((4t+i) & 31)
    }
#pragma unroll 4
    for (int jj = 0; jj < HDIM; jj++) {
        int j = jj ^ t;
        float dv[4];
#pragma unroll
        for (int s = 0; s < 4; s++) dv[s] = din[s * HDIM + j];
#pragma unroll
        for (int i = 0; i < 4; i++) {
            float w = Ws[rowb[i] + (j ^ swz[i])];
#pragma unroll
            for (int s = 0; s < 4; s++) acc[s][i] = fmaf(dv[s], w, acc[s][i]);
        }
    }
}

extern "C" __global__ void __launch_bounds__(256, 1)
ebm_langevin_kernel(const float* __restrict__ x0,
                    const float* __restrict__ w1, const float* __restrict__ b1,
                    const float* __restrict__ w2, const float* __restrict__ b2,
                    const float* __restrict__ w3, const float* __restrict__ b3,
                    const float* __restrict__ w4, const float* __restrict__ b4,
                    const float* __restrict__ w5, const float* __restrict__ b5,
                    const float* __restrict__ noise,
                    float* __restrict__ out)
{
    extern __shared__ float smem[];
    float* w2s  = smem;
    float* w3s  = smem + 16384;
    float* w4s  = smem + 32768;
    float* bufs = smem + 49152;

    const int tid = threadIdx.x;

    // Cooperative swizzled weight load: element (k,j) -> k*128 + (j ^ 4*(k&31)).
    // Done at float4 granularity: slot (k,jg) -> (k, jg ^ (k&31)).
    for (int idx = tid; idx < 3 * 4096; idx += 256) {
        int m   = idx >> 12;
        int rem = idx & 4095;
        int k   = rem >> 5;
        int jg  = rem & 31;
        const float* src = (m == 0) ? w2 : (m == 1) ? w3 : w4;
        float*       dst = (m == 0) ? w2s : (m == 1) ? w3s : w4s;
        reinterpret_cast<float4*>(dst)[k * 32 + (jg ^ (k & 31))] =
            reinterpret_cast<const float4*>(src)[rem];
    }
    __syncthreads();

    const int warp = tid >> 5;
    const int t    = tid & 31;
    float* bufA = bufs + warp * 1024;
    float* bufB = bufA + 512;

    const int gw = blockIdx.x * 8 + warp;
    const int nw = gridDim.x * 8;

    // Small weights hoisted to registers (lane t owns columns 4t..4t+3).
    const float4 w1r0 = ld4(w1 + 4 * t);          // w1[0][4t..]
    const float4 w1r1 = ld4(w1 + HDIM + 4 * t);   // w1[1][4t..]
    const float4 b1v  = ld4(b1 + 4 * t);
    const float4 b2v  = ld4(b2 + 4 * t);
    const float4 b3v  = ld4(b3 + 4 * t);
    const float4 b4v  = ld4(b4 + 4 * t);
    const float4 w5v  = ld4(w5 + 4 * t);
    (void)b5; // energy value itself is never needed for the gradient

    for (int b = gw; b < NCH / 4; b += nw) {
        const int base = b * 4;
        float xs[4][2];
#pragma unroll
        for (int s = 0; s < 4; s++) {               // broadcast loads
            xs[s][0] = x0[(base + s) * 2 + 0];
            xs[s][1] = x0[(base + s) * 2 + 1];
        }

        float sp1[4][4], sp2[4][4], sp3[4][4], sp4[4][4];

        for (int step = 0; step < NSTEPS; step++) {
            // ---- forward L1: 2 -> 128 ----
#pragma unroll
            for (int s = 0; s < 4; s++) {
                float4 hv;
                float a;
                a = fmaf(xs[s][0], w1r0.x, fmaf(xs[s][1], w1r1.x, b1v.x));
                silu_act(a, hv.x, sp1[s][0]);
                a = fmaf(xs[s][0], w1r0.y, fmaf(xs[s][1], w1r1.y, b1v.y));
                silu_act(a, hv.y, sp1[s][1]);
                a = fmaf(xs[s][0], w1r0.z, fmaf(xs[s][1], w1r1.z, b1v.z));
                silu_act(a, hv.z, sp1[s][2]);
                a = fmaf(xs[s][0], w1r0.w, fmaf(xs[s][1], w1r1.w, b1v.w));
                silu_act(a, hv.w, sp1[s][3]);
                st4(bufA + s * HDIM + 4 * t, hv);
            }
            __syncwarp();
            fwd128(w2s, b2v, bufA, bufB, sp2, t);   // h1 -> h2
            __syncwarp();
            fwd128(w3s, b3v, bufB, bufA, sp3, t);   // h2 -> h3
            __syncwarp();
            fwd128(w4s, b4v, bufA, bufB, sp4, t);   // h3 -> h4 (h4 unused)
            __syncwarp();

            // ---- backward ----
            // dE/da4 = w5 * silu'(a4)  -> bufA
#pragma unroll
            for (int s = 0; s < 4; s++) {
                float4 dv;
                dv.x = w5v.x * sp4[s][0];
                dv.y = w5v.y * sp4[s][1];
                dv.z = w5v.z * sp4[s][2];
                dv.w = w5v.w * sp4[s][3];
                st4(bufA + s * HDIM + 4 * t, dv);
            }
            __syncwarp();

            float acc[4][4];
            // dE/dh3 = da4 @ W4^T ; da3 = * silu'(a3) -> bufB
            bwdmm(w4s, bufA, t, acc);
#pragma unroll
            for (int s = 0; s < 4; s++) {
                float4 dv;
                dv.x = acc[s][0] * sp3[s][0];
                dv.y = acc[s][1] * sp3[s][1];
                dv.z = acc[s][2] * sp3[s][2];
                dv.w = acc[s][3] * sp3[s][3];
                st4(bufB + s * HDIM + 4 * t, dv);
            }
            __syncwarp();
            // dE/dh2 = da3 @ W3^T ; da2 = * silu'(a2) -> bufA
            bwdmm(w3s, bufB, t, acc);
#pragma unroll
            for (int s = 0; s < 4; s++) {
                float4 dv;
                dv.x = acc[s][0] * sp2[s][0];
                dv.y = acc[s][1] * sp2[s][1];
                dv.z = acc[s][2] * sp2[s][2];
                dv.w = acc[s][3] * sp2[s][3];
                st4(bufA + s * HDIM + 4 * t, dv);
            }
            __syncwarp();
            // dE/dh1 = da2 @ W2^T ; da1 = * silu'(a1) ; dx = da1 @ W1^T
            bwdmm(w2s, bufA, t, acc);

            float pdx[4][2];
#pragma unroll
            for (int s = 0; s < 4; s++) {
                float d0 = acc[s][0] * sp1[s][0];
                float d1 = acc[s][1] * sp1[s][1];
                float d2 = acc[s][2] * sp1[s][2];
                float d3 = acc[s][3] * sp1[s][3];
                pdx[s][0] = fmaf(d0, w1r0.x, fmaf(d1, w1r0.y,
                            fmaf(d2, w1r0.z, d3 * w1r0.w)));
                pdx[s][1] = fmaf(d0, w1r1.x, fmaf(d1, w1r1.y,
                            fmaf(d2, w1r1.z, d3 * w1r1.w)));
            }
            // butterfly reduce across the warp -> every lane holds full dx
#pragma unroll
            for (int off = 16; off > 0; off >>= 1) {
#pragma unroll
                for (int s = 0; s < 4; s++) {
                    pdx[s][0] += __shfl_xor_sync(0xffffffffu, pdx[s][0], off);
                    pdx[s][1] += __shfl_xor_sync(0xffffffffu, pdx[s][1], off);
                }
            }

            // ---- Langevin update (replicated identically in all lanes) ----
            float fi  = (float)step;
            float eps = 10.0f * (1.0f - fi / 60.0f);
            float sq  = sqrtf(2.0f * eps);
#pragma unroll
            for (int s = 0; s < 4; s++) {
#pragma unroll
                for (int c = 0; c < 2; c++) {
                    float nz = noise[((size_t)step * NCH + base + s) * 2 + c];
                    float g  = fminf(fmaxf(pdx[s][c], -0.03f), 0.03f);
                    float xv = xs[s][c] + sq * nz * 0.005f + eps * g;
                    xs[s][c] = fminf(fmaxf(xv, -2.43f), 3.05f);
                }
            }
            __syncwarp();   // bufA reusable next step
        }

        if (t < 8) {
            int s = t >> 1, c = t & 1;
            out[(base + s) * 2 + c] = xs[s][c];
        }
    }
}

extern "C" void kernel_launch(void* const* d_in, const int* in_sizes, int n_in,
                              void* d_out, int out_size)
{
    const float* x0    = (const float*)d_in[0];
    const float* w1    = (const float*)d_in[1];
    const float* b1    = (const float*)d_in[2];
    const float* w2    = (const float*)d_in[3];
    const float* b2    = (const float*)d_in[4];
    const float* w3    = (const float*)d_in[5];
    const float* b3    = (const float*)d_in[6];
    const float* w4    = (const float*)d_in[7];
    const float* b4    = (const float*)d_in[8];
    const float* w5    = (const float*)d_in[9];
    const float* b5    = (const float*)d_in[10];
    const float* noise = (const float*)d_in[11];

    const int smemBytes = 57344 * (int)sizeof(float);   // 229376
    cudaFuncSetAttribute(ebm_langevin_kernel,
                         cudaFuncAttributeMaxDynamicSharedMemorySize, smemBytes);

    int nsm = 148;
    cudaDeviceGetAttribute(&nsm, cudaDevAttrMultiProcessorCount, 0);

    ebm_langevin_kernel<<<nsm, 256, smemBytes>>>(
        x0, w1, b1, w2, b2, w3, b3, w4, b4, w5, b5, noise, (float*)d_out);
}